// round 1
// baseline (speedup 1.0000x reference)
#include <cuda_runtime.h>
#include <cuda_bf16.h>
#include <cstdint>

// ---------------------------------------------------------------------------
// RNN: h_t = tanh(x_t @ Wx + h_{t-1} @ Wh), out[b,t,:] = h_t
// B=32, L=512, D=1024, fp32.
// Phase 1: xp = x @ Wx written in-place into d_out (one big GEMM).
// Phase 2: persistent kernel, 128 blocks, software grid barrier per step.
// ---------------------------------------------------------------------------

#define B_DIM 32
#define L_DIM 512
#define D_DIM 1024
#define NB 128            // persistent blocks (<= #SMs, 1 CTA/SM due to SMEM)
#define JC 8              // output columns per block (NB*JC == D_DIM)
#define TPB 256
#define HS_STRIDE 1028    // 1024 + 4 pad (bank spread), multiple of 4 for float4
#define WS_STRIDE 1028

__device__ int g_flags[NB];

__global__ void init_flags_kernel() {
    if (threadIdx.x < NB) g_flags[threadIdx.x] = 0;
}

// ---------------------------------------------------------------------------
// Phase 1: C[M,N] = A[M,K] * W[K,N], M=16384, N=K=1024.
// 64x64 block tile, K-tile 16, 256 threads, 4x4 register tile per thread.
// ---------------------------------------------------------------------------
__global__ __launch_bounds__(256) void gemm_xw_kernel(
    const float* __restrict__ A, const float* __restrict__ W,
    float* __restrict__ C)
{
    __shared__ float As[16][64];
    __shared__ float Bs[16][64];

    const int tid = threadIdx.x;
    const int m0 = blockIdx.y * 64;
    const int n0 = blockIdx.x * 64;

    const int aRow = tid >> 2;          // 0..63
    const int aCol = (tid & 3) << 2;    // 0,4,8,12
    const int bRow = tid >> 4;          // 0..15
    const int bCol = (tid & 15) << 2;   // 0..60

    const int ty = tid >> 4;            // 0..15
    const int tx = tid & 15;            // 0..15

    float acc[4][4];
#pragma unroll
    for (int i = 0; i < 4; ++i)
#pragma unroll
        for (int j = 0; j < 4; ++j) acc[i][j] = 0.0f;

    for (int k0 = 0; k0 < D_DIM; k0 += 16) {
        float4 av = *(const float4*)(A + (size_t)(m0 + aRow) * D_DIM + k0 + aCol);
        float4 bv = *(const float4*)(W + (size_t)(k0 + bRow) * D_DIM + n0 + bCol);
        As[aCol + 0][aRow] = av.x;
        As[aCol + 1][aRow] = av.y;
        As[aCol + 2][aRow] = av.z;
        As[aCol + 3][aRow] = av.w;
        *(float4*)&Bs[bRow][bCol] = bv;
        __syncthreads();

#pragma unroll
        for (int kk = 0; kk < 16; ++kk) {
            float4 a = *(const float4*)&As[kk][ty << 2];
            float4 b = *(const float4*)&Bs[kk][tx << 2];
            acc[0][0] = fmaf(a.x, b.x, acc[0][0]);
            acc[0][1] = fmaf(a.x, b.y, acc[0][1]);
            acc[0][2] = fmaf(a.x, b.z, acc[0][2]);
            acc[0][3] = fmaf(a.x, b.w, acc[0][3]);
            acc[1][0] = fmaf(a.y, b.x, acc[1][0]);
            acc[1][1] = fmaf(a.y, b.y, acc[1][1]);
            acc[1][2] = fmaf(a.y, b.z, acc[1][2]);
            acc[1][3] = fmaf(a.y, b.w, acc[1][3]);
            acc[2][0] = fmaf(a.z, b.x, acc[2][0]);
            acc[2][1] = fmaf(a.z, b.y, acc[2][1]);
            acc[2][2] = fmaf(a.z, b.z, acc[2][2]);
            acc[2][3] = fmaf(a.z, b.w, acc[2][3]);
            acc[3][0] = fmaf(a.w, b.x, acc[3][0]);
            acc[3][1] = fmaf(a.w, b.y, acc[3][1]);
            acc[3][2] = fmaf(a.w, b.z, acc[3][2]);
            acc[3][3] = fmaf(a.w, b.w, acc[3][3]);
        }
        __syncthreads();
    }

#pragma unroll
    for (int i = 0; i < 4; ++i) {
        float4 v = make_float4(acc[i][0], acc[i][1], acc[i][2], acc[i][3]);
        *(float4*)(C + (size_t)(m0 + (ty << 2) + i) * D_DIM + n0 + (tx << 2)) = v;
    }
}

// ---------------------------------------------------------------------------
// Phase 2: persistent recurrence kernel.
// Block bid owns output columns [bid*8, bid*8+8).
// SMEM: hs[32][1028] staged h_{t-1}; ws[8][1028] = Wh[:, jslice] transposed.
// Grid barrier: per-block flags, fence -> bar -> flag -> poll -> bar.
// All cross-block data reads use __ldcg (L2) since L1 is incoherent.
// ---------------------------------------------------------------------------
__global__ __launch_bounds__(TPB) void rnn_steps_kernel(
    float* __restrict__ out,           // [B, L, D] : holds xp, overwritten by h
    const float* __restrict__ h0,      // [B, D]
    const float* __restrict__ Wh)      // [D, D]
{
    extern __shared__ float smem[];
    float* hs = smem;                       // 32 * HS_STRIDE
    float* ws = smem + B_DIM * HS_STRIDE;   // JC * WS_STRIDE

    const int tid = threadIdx.x;
    const int bid = blockIdx.x;
    const int j0 = bid * JC;

    // Load Wh column slice, transposed: ws[j][k] = Wh[k][j0+j]
    for (int i = tid; i < JC * D_DIM; i += TPB) {
        int k = i >> 3;        // 0..1023
        int j = i & 7;
        ws[j * WS_STRIDE + k] = Wh[(size_t)k * D_DIM + j0 + j];
    }

    const int b = tid >> 3;    // 0..31
    const int j = tid & 7;     // 0..7
    const float* wrow = ws + j * WS_STRIDE;
    const float* hrow = hs + b * HS_STRIDE;

    __syncthreads();

    for (int t = 0; t < L_DIM; ++t) {
        // ---- stage h_{t-1} into SMEM (L2 reads only) ----
        if (t == 0) {
            for (int i = tid; i < B_DIM * (D_DIM / 4); i += TPB) {
                int bb = i >> 8;
                int k4 = (i & 255) << 2;
                float4 v = __ldcg((const float4*)(h0 + (size_t)bb * D_DIM + k4));
                *(float4*)(hs + bb * HS_STRIDE + k4) = v;
            }
        } else {
            for (int i = tid; i < B_DIM * (D_DIM / 4); i += TPB) {
                int bb = i >> 8;
                int k4 = (i & 255) << 2;
                const float* src = out + ((size_t)bb * L_DIM + (t - 1)) * D_DIM + k4;
                float4 v = __ldcg((const float4*)src);
                *(float4*)(hs + bb * HS_STRIDE + k4) = v;
            }
        }
        __syncthreads();

        // ---- this thread's output: (b, t, j0+j) ----
        const size_t oidx = ((size_t)b * L_DIM + t) * D_DIM + j0 + j;
        float xp = __ldcg(out + oidx);

        float4 acc4 = make_float4(0.f, 0.f, 0.f, 0.f);
#pragma unroll 8
        for (int k = 0; k < D_DIM; k += 4) {
            float4 hv = *(const float4*)(hrow + k);
            float4 wv = *(const float4*)(wrow + k);
            acc4.x = fmaf(hv.x, wv.x, acc4.x);
            acc4.y = fmaf(hv.y, wv.y, acc4.y);
            acc4.z = fmaf(hv.z, wv.z, acc4.z);
            acc4.w = fmaf(hv.w, wv.w, acc4.w);
        }
        float acc = xp + ((acc4.x + acc4.y) + (acc4.z + acc4.w));
        float hval = tanhf(acc);
        out[oidx] = hval;

        // ---- grid barrier ----
        __threadfence();
        __syncthreads();
        if (tid == 0) {
            *((volatile int*)&g_flags[bid]) = t + 1;
        }
        if (tid < NB) {
            while (*((volatile int*)&g_flags[tid]) < t + 1) { }
        }
        __syncthreads();
    }
}

// ---------------------------------------------------------------------------
extern "C" void kernel_launch(void* const* d_in, const int* in_sizes, int n_in,
                              void* d_out, int out_size)
{
    (void)in_sizes; (void)n_in; (void)out_size;
    const float* x  = (const float*)d_in[0];   // [B, L, D]
    const float* h0 = (const float*)d_in[1];   // [B, D]
    const float* Wx = (const float*)d_in[2];   // [D, D]
    const float* Wh = (const float*)d_in[3];   // [D, D]
    float* out = (float*)d_out;                // [B, L, D]

    // Phase 1: xp = x @ Wx  (in place in out)
    dim3 g1(D_DIM / 64, (B_DIM * L_DIM) / 64);
    gemm_xw_kernel<<<g1, 256>>>(x, Wx, out);

    // Phase 2: persistent recurrence
    init_flags_kernel<<<1, NB>>>();
    size_t smem_bytes = (size_t)(B_DIM * HS_STRIDE + JC * WS_STRIDE) * sizeof(float);
    cudaFuncSetAttribute(rnn_steps_kernel,
                         cudaFuncAttributeMaxDynamicSharedMemorySize,
                         (int)smem_bytes);
    rnn_steps_kernel<<<NB, TPB, smem_bytes>>>(out, h0, Wh);
}

// round 3
// speedup vs baseline: 1.2959x; 1.2959x over previous
#include <cuda_runtime.h>
#include <cuda_bf16.h>
#include <cstdint>

// ---------------------------------------------------------------------------
// RNN: h_t = tanh(x_t @ Wx + h_{t-1} @ Wh),  B=32, L=512, D=1024, fp32.
// Phase 1: xp = x @ Wx in-place into d_out (f32x2 SIMT GEMM).
// Phase 2: persistent kernel, Wh in registers, h broadcast from SMEM,
//          packed f32x2 FMAs, pipelined row staging, sw grid barrier.
// ---------------------------------------------------------------------------

#define B_DIM 32
#define L_DIM 512
#define D_DIM 1024
#define NB 128
#define JC 8
#define TPB 256

typedef unsigned long long u64;

__device__ int g_flags[NB];

__global__ void init_flags_kernel() {
    if (threadIdx.x < NB) g_flags[threadIdx.x] = 0;
}

__device__ __forceinline__ u64 pack2(float lo, float hi) {
    u64 r;
    asm("mov.b64 %0, {%1, %2};" : "=l"(r) : "f"(lo), "f"(hi));
    return r;
}
__device__ __forceinline__ void unpack2(u64 v, float& lo, float& hi) {
    asm("mov.b64 {%0, %1}, %2;" : "=f"(lo), "=f"(hi) : "l"(v));
}
__device__ __forceinline__ void ffma2(u64& d, u64 a, u64 b) {
    asm("fma.rn.f32x2 %0, %1, %2, %0;" : "+l"(d) : "l"(a), "l"(b));
}
__device__ __forceinline__ u64 fadd2(u64 a, u64 b) {
    u64 r;
    asm("add.rn.f32x2 %0, %1, %2;" : "=l"(r) : "l"(a), "l"(b));
    return r;
}

// ---------------------------------------------------------------------------
// Phase 1: C[16384,1024] = A[16384,1024] * W[1024,1024]
// 128x64 block tile, BK=16, 256 threads, 8x4 per thread, f32x2 FMAs.
// A staged pre-splatted into SMEM as u64 (a,a); B read as packed n-pairs.
// AS_STRIDE must be EVEN (u64 units) so ulonglong2 reads stay 16B-aligned.
// ---------------------------------------------------------------------------
#define AS_STRIDE 130   // u64 stride per k-row (128 + 2 pad, even!)

__global__ __launch_bounds__(256) void gemm_xw_kernel(
    const float* __restrict__ A, const float* __restrict__ W,
    float* __restrict__ C)
{
    __shared__ __align__(16) u64 As2[16 * AS_STRIDE];   // [k][m] splatted
    __shared__ __align__(16) float Bs[16 * 64];         // [k][n]

    const int tid = threadIdx.x;
    const int m0 = blockIdx.y * 128;
    const int n0 = blockIdx.x * 64;

    const int aRow = tid >> 2;           // 0..63
    const int aCol = (tid & 3) << 2;     // 0,4,8,12
    const int bRow = tid >> 4;           // 0..15
    const int bCol = (tid & 15) << 2;    // 0..60

    const int ty = tid >> 4;             // 0..15 -> m = ty*8
    const int tx = tid & 15;             // 0..15 -> n = tx*4

    u64 acc[8][2];
#pragma unroll
    for (int m = 0; m < 8; ++m) { acc[m][0] = 0ull; acc[m][1] = 0ull; }

    for (int k0 = 0; k0 < D_DIM; k0 += 16) {
        float4 av0 = *(const float4*)(A + (size_t)(m0 + aRow) * D_DIM + k0 + aCol);
        float4 av1 = *(const float4*)(A + (size_t)(m0 + aRow + 64) * D_DIM + k0 + aCol);
        float4 bv  = *(const float4*)(W + (size_t)(k0 + bRow) * D_DIM + n0 + bCol);

        As2[(aCol + 0) * AS_STRIDE + aRow] = pack2(av0.x, av0.x);
        As2[(aCol + 1) * AS_STRIDE + aRow] = pack2(av0.y, av0.y);
        As2[(aCol + 2) * AS_STRIDE + aRow] = pack2(av0.z, av0.z);
        As2[(aCol + 3) * AS_STRIDE + aRow] = pack2(av0.w, av0.w);
        As2[(aCol + 0) * AS_STRIDE + aRow + 64] = pack2(av1.x, av1.x);
        As2[(aCol + 1) * AS_STRIDE + aRow + 64] = pack2(av1.y, av1.y);
        As2[(aCol + 2) * AS_STRIDE + aRow + 64] = pack2(av1.z, av1.z);
        As2[(aCol + 3) * AS_STRIDE + aRow + 64] = pack2(av1.w, av1.w);
        *(float4*)&Bs[bRow * 64 + bCol] = bv;
        __syncthreads();

#pragma unroll
        for (int kk = 0; kk < 16; ++kk) {
            const u64* ap = As2 + kk * AS_STRIDE + ty * 8;
            ulonglong2 a01 = *(const ulonglong2*)(ap + 0);
            ulonglong2 a23 = *(const ulonglong2*)(ap + 2);
            ulonglong2 a45 = *(const ulonglong2*)(ap + 4);
            ulonglong2 a67 = *(const ulonglong2*)(ap + 6);
            ulonglong2 bp  = *(const ulonglong2*)(Bs + kk * 64 + tx * 4);
            ffma2(acc[0][0], a01.x, bp.x); ffma2(acc[0][1], a01.x, bp.y);
            ffma2(acc[1][0], a01.y, bp.x); ffma2(acc[1][1], a01.y, bp.y);
            ffma2(acc[2][0], a23.x, bp.x); ffma2(acc[2][1], a23.x, bp.y);
            ffma2(acc[3][0], a23.y, bp.x); ffma2(acc[3][1], a23.y, bp.y);
            ffma2(acc[4][0], a45.x, bp.x); ffma2(acc[4][1], a45.x, bp.y);
            ffma2(acc[5][0], a45.y, bp.x); ffma2(acc[5][1], a45.y, bp.y);
            ffma2(acc[6][0], a67.x, bp.x); ffma2(acc[6][1], a67.x, bp.y);
            ffma2(acc[7][0], a67.y, bp.x); ffma2(acc[7][1], a67.y, bp.y);
        }
        __syncthreads();
    }

#pragma unroll
    for (int m = 0; m < 8; ++m) {
        float4 v;
        unpack2(acc[m][0], v.x, v.y);
        unpack2(acc[m][1], v.z, v.w);
        *(float4*)(C + (size_t)(m0 + ty * 8 + m) * D_DIM + n0 + tx * 4) = v;
    }
}

// ---------------------------------------------------------------------------
// Phase 2: persistent recurrence.
// Block bid owns columns [bid*8, bid*8+8).
// Warp w covers k in [w*128, w*128+128). lane = j*4 + q.
// Thread's k values: k = w*128 + i*16 + q*4 + c  (i=0..7, c=0..3)
//   -> per LDS.128, the 4 q-addresses are 16B-consecutive (1 wavefront,
//      8-way j-broadcast), and Wh stays in registers forever.
// ---------------------------------------------------------------------------
#define PART_OFF (B_DIM * D_DIM)                 // floats
#define SMEM2_FLOATS (PART_OFF + B_DIM * JC * 9)

__global__ __launch_bounds__(TPB) void rnn_steps_kernel(
    float* __restrict__ out,          // [B, L, D]: holds xp, overwritten by h
    const float* __restrict__ h0,     // [B, D]
    const float* __restrict__ Wh)     // [D, D]
{
    extern __shared__ __align__(16) float smem[];
    float* hs   = smem;               // [32][1024]
    float* part = smem + PART_OFF;    // [32][8][9]

    const int tid  = threadIdx.x;
    const int bid  = blockIdx.x;
    const int w    = tid >> 5;
    const int lane = tid & 31;
    const int j    = lane >> 2;       // 0..7
    const int q    = lane & 3;        // 0..3
    const int j0   = bid * JC;

    // Wh registers: wreg[i*2+p] packs W[k(i,c=2p)][j0+j], W[k(i,c=2p+1)][j0+j]
    u64 wreg[16];
#pragma unroll
    for (int i = 0; i < 8; ++i) {
        int kb = w * 128 + i * 16 + q * 4;
        float w0 = Wh[(size_t)(kb + 0) * D_DIM + j0 + j];
        float w1 = Wh[(size_t)(kb + 1) * D_DIM + j0 + j];
        float w2 = Wh[(size_t)(kb + 2) * D_DIM + j0 + j];
        float w3 = Wh[(size_t)(kb + 3) * D_DIM + j0 + j];
        wreg[i * 2 + 0] = pack2(w0, w1);
        wreg[i * 2 + 1] = pack2(w2, w3);
    }

    const int ob = tid >> 3;          // 0..31 (output batch for final reduce)
    const int oj = tid & 7;           // 0..7
    const int hoff = w * 128 + q * 4; // this thread's k base within a row

    for (int t = 0; t < L_DIM; ++t) {
        const float* srcbase;
        size_t rstride;
        if (t == 0) { srcbase = h0; rstride = D_DIM; }
        else        { srcbase = out + (size_t)(t - 1) * D_DIM; rstride = (size_t)L_DIM * D_DIM; }

        float xp = out[((size_t)ob * L_DIM + t) * D_DIM + j0 + oj];

        // prologue: load rows 0..7
        float4 buf[8];
#pragma unroll
        for (int r = 0; r < 8; ++r)
            buf[r] = __ldcg((const float4*)(srcbase + (size_t)r * rstride + tid * 4));

#pragma unroll
        for (int g = 0; g < 4; ++g) {
#pragma unroll
            for (int r = 0; r < 8; ++r)
                *(float4*)(hs + (size_t)(g * 8 + r) * D_DIM + tid * 4) = buf[r];
            __syncthreads();
            if (g < 3) {
#pragma unroll
                for (int r = 0; r < 8; ++r)
                    buf[r] = __ldcg((const float4*)(srcbase + (size_t)(g * 8 + 8 + r) * rstride + tid * 4));
            }
#pragma unroll 2
            for (int bb = 0; bb < 8; ++bb) {
                const int b = g * 8 + bb;
                const float* hb = hs + b * D_DIM + hoff;
                u64 acc0 = 0ull, acc1 = 0ull, acc2 = 0ull, acc3 = 0ull;
#pragma unroll
                for (int i = 0; i < 8; i += 2) {
                    ulonglong2 h0v = *(const ulonglong2*)(hb + i * 16);
                    ulonglong2 h1v = *(const ulonglong2*)(hb + i * 16 + 16);
                    ffma2(acc0, h0v.x, wreg[i * 2 + 0]);
                    ffma2(acc1, h0v.y, wreg[i * 2 + 1]);
                    ffma2(acc2, h1v.x, wreg[i * 2 + 2]);
                    ffma2(acc3, h1v.y, wreg[i * 2 + 3]);
                }
                u64 accs = fadd2(fadd2(acc0, acc1), fadd2(acc2, acc3));
                float lo, hi;
                unpack2(accs, lo, hi);
                float s = lo + hi;
                s += __shfl_xor_sync(0xffffffffu, s, 1);
                s += __shfl_xor_sync(0xffffffffu, s, 2);
                if (q == 0) part[(b * JC + j) * 9 + w] = s;
            }
        }
        __syncthreads();

        // final reduce over 8 warps + tanh + store (one output per thread)
        const float* pr = part + (ob * JC + oj) * 9;
        float tot = xp;
#pragma unroll
        for (int ww = 0; ww < 8; ++ww) tot += pr[ww];
        out[((size_t)ob * L_DIM + t) * D_DIM + j0 + oj] = tanhf(tot);

        // grid barrier
        __threadfence();
        __syncthreads();
        if (tid == 0) *((volatile int*)&g_flags[bid]) = t + 1;
        if (tid < NB) {
            while (*((volatile int*)&g_flags[tid]) < t + 1) { }
        }
        __syncthreads();
    }
}

// ---------------------------------------------------------------------------
extern "C" void kernel_launch(void* const* d_in, const int* in_sizes, int n_in,
                              void* d_out, int out_size)
{
    (void)in_sizes; (void)n_in; (void)out_size;
    const float* x  = (const float*)d_in[0];
    const float* h0 = (const float*)d_in[1];
    const float* Wx = (const float*)d_in[2];
    const float* Wh = (const float*)d_in[3];
    float* out = (float*)d_out;

    dim3 g1(D_DIM / 64, (B_DIM * L_DIM) / 128);
    gemm_xw_kernel<<<g1, 256>>>(x, Wx, out);

    init_flags_kernel<<<1, NB>>>();
    size_t smem_bytes = (size_t)SMEM2_FLOATS * sizeof(float);
    cudaFuncSetAttribute(rnn_steps_kernel,
                         cudaFuncAttributeMaxDynamicSharedMemorySize,
                         (int)smem_bytes);
    rnn_steps_kernel<<<NB, TPB, smem_bytes>>>(out, h0, Wh);
}

// round 4
// speedup vs baseline: 3.5228x; 2.7183x over previous
#include <cuda_runtime.h>
#include <cuda_bf16.h>
#include <cstdint>

// ---------------------------------------------------------------------------
// RNN: h_t = tanh(x_t @ Wx + h_{t-1} @ Wh),  B=32, L=512, D=1024, fp32.
// Phase 1: xp = x @ Wx in-place into d_out (f32x2 SIMT GEMM).
// Phase 2: persistent kernel. Block (bq,jg) owns 8 batch rows x 32 columns.
//          Thread owns 4 columns x 32 k -> 8 FFMA2 per LDS.128.
//          Counter barrier: red.release arrive + single-thread acquire poll.
// ---------------------------------------------------------------------------

#define B_DIM 32
#define L_DIM 512
#define D_DIM 1024
#define NB 128
#define TPB 256

#define HROW_F 1152            // staged row: 32 chunks * (32 floats + 4 pad)
#define PART_STRIDE 36
#define HS_FLOATS (8 * HROW_F)
#define PART_OFF HS_FLOATS
#define PART_FLOATS (8 * 32 * PART_STRIDE)
#define SMEM2_FLOATS (PART_OFF + PART_FLOATS)

typedef unsigned long long u64;

__device__ unsigned g_ctr;

__global__ void init_flags_kernel() {
    if (threadIdx.x == 0) g_ctr = 0u;
}

__device__ __forceinline__ u64 pack2(float lo, float hi) {
    u64 r;
    asm("mov.b64 %0, {%1, %2};" : "=l"(r) : "f"(lo), "f"(hi));
    return r;
}
__device__ __forceinline__ void unpack2(u64 v, float& lo, float& hi) {
    asm("mov.b64 {%0, %1}, %2;" : "=f"(lo), "=f"(hi) : "l"(v));
}
__device__ __forceinline__ void ffma2(u64& d, u64 a, u64 b) {
    asm("fma.rn.f32x2 %0, %1, %2, %0;" : "+l"(d) : "l"(a), "l"(b));
}

// ---------------------------------------------------------------------------
// Phase 1: C[16384,1024] = A[16384,1024] * W[1024,1024]
// 128x64 block tile, BK=16, 256 threads, 8x4 per thread, f32x2 FMAs.
// ---------------------------------------------------------------------------
#define AS_STRIDE 130   // u64 stride per k-row (even -> 16B-aligned reads)

__global__ __launch_bounds__(256) void gemm_xw_kernel(
    const float* __restrict__ A, const float* __restrict__ W,
    float* __restrict__ C)
{
    __shared__ __align__(16) u64 As2[16 * AS_STRIDE];
    __shared__ __align__(16) float Bs[16 * 64];

    const int tid = threadIdx.x;
    const int m0 = blockIdx.y * 128;
    const int n0 = blockIdx.x * 64;

    const int aRow = tid >> 2;
    const int aCol = (tid & 3) << 2;
    const int bRow = tid >> 4;
    const int bCol = (tid & 15) << 2;

    const int ty = tid >> 4;
    const int tx = tid & 15;

    u64 acc[8][2];
#pragma unroll
    for (int m = 0; m < 8; ++m) { acc[m][0] = 0ull; acc[m][1] = 0ull; }

    for (int k0 = 0; k0 < D_DIM; k0 += 16) {
        float4 av0 = *(const float4*)(A + (size_t)(m0 + aRow) * D_DIM + k0 + aCol);
        float4 av1 = *(const float4*)(A + (size_t)(m0 + aRow + 64) * D_DIM + k0 + aCol);
        float4 bv  = *(const float4*)(W + (size_t)(k0 + bRow) * D_DIM + n0 + bCol);

        As2[(aCol + 0) * AS_STRIDE + aRow] = pack2(av0.x, av0.x);
        As2[(aCol + 1) * AS_STRIDE + aRow] = pack2(av0.y, av0.y);
        As2[(aCol + 2) * AS_STRIDE + aRow] = pack2(av0.z, av0.z);
        As2[(aCol + 3) * AS_STRIDE + aRow] = pack2(av0.w, av0.w);
        As2[(aCol + 0) * AS_STRIDE + aRow + 64] = pack2(av1.x, av1.x);
        As2[(aCol + 1) * AS_STRIDE + aRow + 64] = pack2(av1.y, av1.y);
        As2[(aCol + 2) * AS_STRIDE + aRow + 64] = pack2(av1.z, av1.z);
        As2[(aCol + 3) * AS_STRIDE + aRow + 64] = pack2(av1.w, av1.w);
        *(float4*)&Bs[bRow * 64 + bCol] = bv;
        __syncthreads();

#pragma unroll
        for (int kk = 0; kk < 16; ++kk) {
            const u64* ap = As2 + kk * AS_STRIDE + ty * 8;
            ulonglong2 a01 = *(const ulonglong2*)(ap + 0);
            ulonglong2 a23 = *(const ulonglong2*)(ap + 2);
            ulonglong2 a45 = *(const ulonglong2*)(ap + 4);
            ulonglong2 a67 = *(const ulonglong2*)(ap + 6);
            ulonglong2 bp  = *(const ulonglong2*)(Bs + kk * 64 + tx * 4);
            ffma2(acc[0][0], a01.x, bp.x); ffma2(acc[0][1], a01.x, bp.y);
            ffma2(acc[1][0], a01.y, bp.x); ffma2(acc[1][1], a01.y, bp.y);
            ffma2(acc[2][0], a23.x, bp.x); ffma2(acc[2][1], a23.x, bp.y);
            ffma2(acc[3][0], a23.y, bp.x); ffma2(acc[3][1], a23.y, bp.y);
            ffma2(acc[4][0], a45.x, bp.x); ffma2(acc[4][1], a45.x, bp.y);
            ffma2(acc[5][0], a45.y, bp.x); ffma2(acc[5][1], a45.y, bp.y);
            ffma2(acc[6][0], a67.x, bp.x); ffma2(acc[6][1], a67.x, bp.y);
            ffma2(acc[7][0], a67.y, bp.x); ffma2(acc[7][1], a67.y, bp.y);
        }
        __syncthreads();
    }

#pragma unroll
    for (int m = 0; m < 8; ++m) {
        float4 v;
        unpack2(acc[m][0], v.x, v.y);
        unpack2(acc[m][1], v.z, v.w);
        *(float4*)(C + (size_t)(m0 + ty * 8 + m) * D_DIM + n0 + tx * 4) = v;
    }
}

// ---------------------------------------------------------------------------
// Phase 2: persistent recurrence.
// bid -> (bq = bid>>5 owns b in [bq*8, bq*8+8), jg = bid&31 owns 32 columns).
// Thread (warp, lane): jq = lane&7 -> 4 columns; kc = warp*4 + (lane>>3)
//   -> 32 k. Weights: wreg[4][16] u64 k-pairs, resident all 512 steps.
// h rows staged into SMEM with 16B pad per 128B chunk (conflict-free reads:
// 4 distinct addresses per warp, 8-way broadcast, banks offset by pad).
// ---------------------------------------------------------------------------
__global__ __launch_bounds__(TPB, 1) void rnn_steps_kernel(
    float* __restrict__ out,          // [B, L, D]: holds xp, overwritten by h
    const float* __restrict__ h0,     // [B, D]
    const float* __restrict__ Wh)     // [D, D]
{
    extern __shared__ __align__(16) float smem[];
    float* hs   = smem;               // 8 rows * HROW_F
    float* part = smem + PART_OFF;    // [8*32][36]

    const int tid  = threadIdx.x;
    const int warp = tid >> 5;
    const int lane = tid & 31;
    const int bid  = blockIdx.x;
    const int jg = bid & 31, bq = bid >> 5;
    const int j0 = jg * 32, b0 = bq * 8;
    const int jq = lane & 7;                    // column group (4 cols)
    const int kc = (warp << 2) | (lane >> 3);   // k-chunk 0..31
    const int kb = kc * 32;

    // Wh registers: wreg[jl][kk] packs Wh[kb+2kk][jcol], Wh[kb+2kk+1][jcol]
    u64 wreg[4][16];
#pragma unroll
    for (int jl = 0; jl < 4; ++jl) {
        const int jcol = j0 + jq * 4 + jl;
#pragma unroll
        for (int kk = 0; kk < 16; ++kk) {
            float w0 = Wh[(size_t)(kb + 2 * kk)     * D_DIM + jcol];
            float w1 = Wh[(size_t)(kb + 2 * kk + 1) * D_DIM + jcol];
            wreg[jl][kk] = pack2(w0, w1);
        }
    }

    unsigned* ctr = &g_ctr;

    for (int t = 0; t < L_DIM; ++t) {
        // xp for this thread's output (b = warp row, j = lane)
        const size_t orow = ((size_t)(b0 + warp) * L_DIM + t) * D_DIM + j0 + lane;
        float xp = out[orow];

        // ---- stage h_{t-1}: warp w stages row b0+w (1024 floats) ----
        const float* src = (t == 0)
            ? (h0 + (size_t)(b0 + warp) * D_DIM)
            : (out + ((size_t)(b0 + warp) * L_DIM + (t - 1)) * D_DIM);
#pragma unroll
        for (int half = 0; half < 2; ++half) {
            float4 v[4];
#pragma unroll
            for (int m = 0; m < 4; ++m)
                v[m] = __ldcg((const float4*)(src + ((half * 4 + m) * 32 + lane) * 4));
#pragma unroll
            for (int m = 0; m < 4; ++m) {
                int idx = (half * 4 + m) * 32 + lane;    // float4 index in row
                *(float4*)(hs + warp * HROW_F + (idx >> 3) * 36 + (idx & 7) * 4) = v[m];
            }
        }
        __syncthreads();

        // ---- compute: 8 b x 4 j x 32 k per thread ----
        u64 acc[8][4];
#pragma unroll
        for (int b = 0; b < 8; ++b)
#pragma unroll
            for (int jl = 0; jl < 4; ++jl) acc[b][jl] = 0ull;

#pragma unroll
        for (int b = 0; b < 8; ++b) {
            const ulonglong2* hb = (const ulonglong2*)(hs + b * HROW_F + kc * 36);
#pragma unroll
            for (int i = 0; i < 8; ++i) {
                ulonglong2 hp = hb[i];
                ffma2(acc[b][0], hp.x, wreg[0][2 * i]);
                ffma2(acc[b][1], hp.x, wreg[1][2 * i]);
                ffma2(acc[b][2], hp.x, wreg[2][2 * i]);
                ffma2(acc[b][3], hp.x, wreg[3][2 * i]);
                ffma2(acc[b][0], hp.y, wreg[0][2 * i + 1]);
                ffma2(acc[b][1], hp.y, wreg[1][2 * i + 1]);
                ffma2(acc[b][2], hp.y, wreg[2][2 * i + 1]);
                ffma2(acc[b][3], hp.y, wreg[3][2 * i + 1]);
            }
        }

        // ---- fold accumulators, store partials ----
#pragma unroll
        for (int b = 0; b < 8; ++b)
#pragma unroll
            for (int jl = 0; jl < 4; ++jl) {
                float lo, hi;
                unpack2(acc[b][jl], lo, hi);
                part[(b * 32 + jq * 4 + jl) * PART_STRIDE + kc] = lo + hi;
            }
        __syncthreads();

        // ---- final reduce over 32 k-chunks + tanh + store ----
        float s = xp;
        const float* pr = part + (warp * 32 + lane) * PART_STRIDE;
#pragma unroll
        for (int g = 0; g < 8; ++g) {
            float4 p = *(const float4*)(pr + g * 4);
            s += (p.x + p.y) + (p.z + p.w);
        }
        out[orow] = tanhf(s);

        // ---- grid barrier: counter arrive + single-thread acquire poll ----
        __syncthreads();   // all STG issued; also protects hs/part reuse
        if (tid == 0) {
            asm volatile("red.release.gpu.add.u32 [%0], 1;" :: "l"(ctr) : "memory");
            const unsigned target = (unsigned)NB * (unsigned)(t + 1);
            unsigned v;
            while (true) {
                asm volatile("ld.acquire.gpu.u32 %0, [%1];" : "=r"(v) : "l"(ctr) : "memory");
                if (v >= target) break;
                __nanosleep(32);
            }
        }
        __syncthreads();
    }
}

// ---------------------------------------------------------------------------
extern "C" void kernel_launch(void* const* d_in, const int* in_sizes, int n_in,
                              void* d_out, int out_size)
{
    (void)in_sizes; (void)n_in; (void)out_size;
    const float* x  = (const float*)d_in[0];
    const float* h0 = (const float*)d_in[1];
    const float* Wx = (const float*)d_in[2];
    const float* Wh = (const float*)d_in[3];
    float* out = (float*)d_out;

    dim3 g1(D_DIM / 64, (B_DIM * L_DIM) / 128);
    gemm_xw_kernel<<<g1, 256>>>(x, Wx, out);

    init_flags_kernel<<<1, 32>>>();
    size_t smem_bytes = (size_t)SMEM2_FLOATS * sizeof(float);
    cudaFuncSetAttribute(rnn_steps_kernel,
                         cudaFuncAttributeMaxDynamicSharedMemorySize,
                         (int)smem_bytes);
    rnn_steps_kernel<<<NB, TPB, smem_bytes>>>(out, h0, Wh);
}

// round 5
// speedup vs baseline: 3.8686x; 1.0982x over previous
#include <cuda_runtime.h>
#include <cuda_bf16.h>
#include <cstdint>

// ---------------------------------------------------------------------------
// RNN: h_t = tanh(x_t @ Wx + h_{t-1} @ Wh),  B=32, L=512, D=1024, fp32.
// Phase 1: xp = x @ Wx in-place into d_out (f32x2 SIMT GEMM, double-buffered).
// Phase 2: persistent kernel; 4 independent batch groups, each with its own
//          32-block counter barrier; Wh in registers; xp(t+1) prefetch.
// ---------------------------------------------------------------------------

#define B_DIM 32
#define L_DIM 512
#define D_DIM 1024
#define NB 128
#define TPB 256

#define HROW_F 1152            // staged row: 32 chunks * (32 floats + 4 pad)
#define PART_STRIDE 36
#define HS_FLOATS (8 * HROW_F)
#define PART_OFF HS_FLOATS
#define PART_FLOATS (8 * 32 * PART_STRIDE)
#define SMEM2_FLOATS (PART_OFF + PART_FLOATS)

typedef unsigned long long u64;

__device__ unsigned g_ctrs[4];

__global__ void init_flags_kernel() {
    if (threadIdx.x < 4) g_ctrs[threadIdx.x] = 0u;
}

__device__ __forceinline__ u64 pack2(float lo, float hi) {
    u64 r;
    asm("mov.b64 %0, {%1, %2};" : "=l"(r) : "f"(lo), "f"(hi));
    return r;
}
__device__ __forceinline__ void unpack2(u64 v, float& lo, float& hi) {
    asm("mov.b64 {%0, %1}, %2;" : "=f"(lo), "=f"(hi) : "l"(v));
}
__device__ __forceinline__ void ffma2(u64& d, u64 a, u64 b) {
    asm("fma.rn.f32x2 %0, %1, %2, %0;" : "+l"(d) : "l"(a), "l"(b));
}

// ---------------------------------------------------------------------------
// Phase 1: C[16384,1024] = A[16384,1024] * W[1024,1024]
// 128x64 block tile, BK=16, 256 threads, 8x4 per thread, f32x2 FMAs.
// Double-buffered SMEM; next tile's LDGs issued before current compute.
// ---------------------------------------------------------------------------
#define AS_STRIDE 130   // u64 stride per k-row (even -> 16B-aligned reads)

__global__ __launch_bounds__(256) void gemm_xw_kernel(
    const float* __restrict__ A, const float* __restrict__ W,
    float* __restrict__ C)
{
    __shared__ __align__(16) u64 As2[2][16 * AS_STRIDE];
    __shared__ __align__(16) float Bs[2][16 * 64];

    const int tid = threadIdx.x;
    const int m0 = blockIdx.y * 128;
    const int n0 = blockIdx.x * 64;

    const int aRow = tid >> 2;
    const int aCol = (tid & 3) << 2;
    const int bRow = tid >> 4;
    const int bCol = (tid & 15) << 2;

    const int ty = tid >> 4;
    const int tx = tid & 15;

    const float* aPtr0 = A + (size_t)(m0 + aRow) * D_DIM + aCol;
    const float* aPtr1 = A + (size_t)(m0 + aRow + 64) * D_DIM + aCol;
    const float* bPtr  = W + (size_t)bRow * D_DIM + n0 + bCol;

    u64 acc[8][2];
#pragma unroll
    for (int m = 0; m < 8; ++m) { acc[m][0] = 0ull; acc[m][1] = 0ull; }

    // prologue: tile 0 into buffer 0
    {
        float4 av0 = *(const float4*)(aPtr0);
        float4 av1 = *(const float4*)(aPtr1);
        float4 bv  = *(const float4*)(bPtr);
        u64* as = As2[0];
        as[(aCol + 0) * AS_STRIDE + aRow] = pack2(av0.x, av0.x);
        as[(aCol + 1) * AS_STRIDE + aRow] = pack2(av0.y, av0.y);
        as[(aCol + 2) * AS_STRIDE + aRow] = pack2(av0.z, av0.z);
        as[(aCol + 3) * AS_STRIDE + aRow] = pack2(av0.w, av0.w);
        as[(aCol + 0) * AS_STRIDE + aRow + 64] = pack2(av1.x, av1.x);
        as[(aCol + 1) * AS_STRIDE + aRow + 64] = pack2(av1.y, av1.y);
        as[(aCol + 2) * AS_STRIDE + aRow + 64] = pack2(av1.z, av1.z);
        as[(aCol + 3) * AS_STRIDE + aRow + 64] = pack2(av1.w, av1.w);
        *(float4*)&Bs[0][bRow * 64 + bCol] = bv;
    }
    __syncthreads();

    int cur = 0;
    for (int k0 = 0; k0 < D_DIM; k0 += 16) {
        // prefetch next tile (LDGs issued before compute)
        float4 nav0, nav1, nbv;
        const bool more = (k0 + 16) < D_DIM;
        if (more) {
            nav0 = *(const float4*)(aPtr0 + k0 + 16);
            nav1 = *(const float4*)(aPtr1 + k0 + 16);
            nbv  = *(const float4*)(bPtr + (size_t)(k0 + 16) * D_DIM);
        }

        const u64* asb = As2[cur];
        const float* bsb = Bs[cur];
#pragma unroll
        for (int kk = 0; kk < 16; ++kk) {
            const u64* ap = asb + kk * AS_STRIDE + ty * 8;
            ulonglong2 a01 = *(const ulonglong2*)(ap + 0);
            ulonglong2 a23 = *(const ulonglong2*)(ap + 2);
            ulonglong2 a45 = *(const ulonglong2*)(ap + 4);
            ulonglong2 a67 = *(const ulonglong2*)(ap + 6);
            ulonglong2 bp  = *(const ulonglong2*)(bsb + kk * 64 + tx * 4);
            ffma2(acc[0][0], a01.x, bp.x); ffma2(acc[0][1], a01.x, bp.y);
            ffma2(acc[1][0], a01.y, bp.x); ffma2(acc[1][1], a01.y, bp.y);
            ffma2(acc[2][0], a23.x, bp.x); ffma2(acc[2][1], a23.x, bp.y);
            ffma2(acc[3][0], a23.y, bp.x); ffma2(acc[3][1], a23.y, bp.y);
            ffma2(acc[4][0], a45.x, bp.x); ffma2(acc[4][1], a45.x, bp.y);
            ffma2(acc[5][0], a45.y, bp.x); ffma2(acc[5][1], a45.y, bp.y);
            ffma2(acc[6][0], a67.x, bp.x); ffma2(acc[6][1], a67.x, bp.y);
            ffma2(acc[7][0], a67.y, bp.x); ffma2(acc[7][1], a67.y, bp.y);
        }

        if (more) {
            u64* as = As2[cur ^ 1];
            as[(aCol + 0) * AS_STRIDE + aRow] = pack2(nav0.x, nav0.x);
            as[(aCol + 1) * AS_STRIDE + aRow] = pack2(nav0.y, nav0.y);
            as[(aCol + 2) * AS_STRIDE + aRow] = pack2(nav0.z, nav0.z);
            as[(aCol + 3) * AS_STRIDE + aRow] = pack2(nav0.w, nav0.w);
            as[(aCol + 0) * AS_STRIDE + aRow + 64] = pack2(nav1.x, nav1.x);
            as[(aCol + 1) * AS_STRIDE + aRow + 64] = pack2(nav1.y, nav1.y);
            as[(aCol + 2) * AS_STRIDE + aRow + 64] = pack2(nav1.z, nav1.z);
            as[(aCol + 3) * AS_STRIDE + aRow + 64] = pack2(nav1.w, nav1.w);
            *(float4*)&Bs[cur ^ 1][bRow * 64 + bCol] = nbv;
            __syncthreads();
        }
        cur ^= 1;
    }

#pragma unroll
    for (int m = 0; m < 8; ++m) {
        float4 v;
        unpack2(acc[m][0], v.x, v.y);
        unpack2(acc[m][1], v.z, v.w);
        *(float4*)(C + (size_t)(m0 + ty * 8 + m) * D_DIM + n0 + tx * 4) = v;
    }
}

// ---------------------------------------------------------------------------
// Phase 2: persistent recurrence.
// bid -> (bq = bid>>5 owns b in [bq*8, bq*8+8), jg = bid&31 owns 32 columns).
// The 4 bq groups are independent recurrences -> independent barriers.
// Thread: jq = lane&7 -> 4 columns; kc = warp*4 + (lane>>3) -> 32 k.
// ---------------------------------------------------------------------------
__global__ __launch_bounds__(TPB, 1) void rnn_steps_kernel(
    float* __restrict__ out,          // [B, L, D]: holds xp, overwritten by h
    const float* __restrict__ h0,     // [B, D]
    const float* __restrict__ Wh)     // [D, D]
{
    extern __shared__ __align__(16) float smem[];
    float* hs   = smem;               // 8 rows * HROW_F
    float* part = smem + PART_OFF;    // [8*32][36]

    const int tid  = threadIdx.x;
    const int warp = tid >> 5;
    const int lane = tid & 31;
    const int bid  = blockIdx.x;
    const int jg = bid & 31, bq = bid >> 5;
    const int j0 = jg * 32, b0 = bq * 8;
    const int jq = lane & 7;                    // column group (4 cols)
    const int kc = (warp << 2) | (lane >> 3);   // k-chunk 0..31
    const int kb = kc * 32;

    // Wh registers: wreg[jl][kk] packs Wh[kb+2kk][jcol], Wh[kb+2kk+1][jcol]
    u64 wreg[4][16];
#pragma unroll
    for (int jl = 0; jl < 4; ++jl) {
        const int jcol = j0 + jq * 4 + jl;
#pragma unroll
        for (int kk = 0; kk < 16; ++kk) {
            float w0 = Wh[(size_t)(kb + 2 * kk)     * D_DIM + jcol];
            float w1 = Wh[(size_t)(kb + 2 * kk + 1) * D_DIM + jcol];
            wreg[jl][kk] = pack2(w0, w1);
        }
    }

    unsigned* ctr = &g_ctrs[bq];
    const size_t obase = ((size_t)(b0 + warp) * L_DIM) * D_DIM + j0 + lane;

    float xp = out[obase];            // xp for t=0 (phase-1 result)

    for (int t = 0; t < L_DIM; ++t) {
        const size_t orow = obase + (size_t)t * D_DIM;

        // ---- stage h_{t-1}: warp w stages row b0+w (1024 floats) ----
        const float* src = (t == 0)
            ? (h0 + (size_t)(b0 + warp) * D_DIM)
            : (out + ((size_t)(b0 + warp) * L_DIM + (t - 1)) * D_DIM);
#pragma unroll
        for (int half = 0; half < 2; ++half) {
            float4 v[4];
#pragma unroll
            for (int m = 0; m < 4; ++m)
                v[m] = __ldcg((const float4*)(src + ((half * 4 + m) * 32 + lane) * 4));
#pragma unroll
            for (int m = 0; m < 4; ++m) {
                int idx = (half * 4 + m) * 32 + lane;    // float4 index in row
                *(float4*)(hs + warp * HROW_F + (idx >> 3) * 36 + (idx & 7) * 4) = v[m];
            }
        }
        __syncthreads();

        // ---- compute: 8 b x 4 j x 32 k per thread ----
        u64 acc[8][4];
#pragma unroll
        for (int b = 0; b < 8; ++b)
#pragma unroll
            for (int jl = 0; jl < 4; ++jl) acc[b][jl] = 0ull;

#pragma unroll
        for (int b = 0; b < 8; ++b) {
            const ulonglong2* hb = (const ulonglong2*)(hs + b * HROW_F + kc * 36);
#pragma unroll
            for (int i = 0; i < 8; ++i) {
                ulonglong2 hp = hb[i];
                ffma2(acc[b][0], hp.x, wreg[0][2 * i]);
                ffma2(acc[b][1], hp.x, wreg[1][2 * i]);
                ffma2(acc[b][2], hp.x, wreg[2][2 * i]);
                ffma2(acc[b][3], hp.x, wreg[3][2 * i]);
                ffma2(acc[b][0], hp.y, wreg[0][2 * i + 1]);
                ffma2(acc[b][1], hp.y, wreg[1][2 * i + 1]);
                ffma2(acc[b][2], hp.y, wreg[2][2 * i + 1]);
                ffma2(acc[b][3], hp.y, wreg[3][2 * i + 1]);
            }
        }

        // ---- fold accumulators, store partials ----
#pragma unroll
        for (int b = 0; b < 8; ++b)
#pragma unroll
            for (int jl = 0; jl < 4; ++jl) {
                float lo, hi;
                unpack2(acc[b][jl], lo, hi);
                part[(b * 32 + jq * 4 + jl) * PART_STRIDE + kc] = lo + hi;
            }

        // prefetch xp for step t+1 (this slot is written only by this thread,
        // and only at step t+1 -> safe to read early, hides latency in barrier)
        float xp_next = 0.0f;
        if (t + 1 < L_DIM) xp_next = out[orow + D_DIM];

        __syncthreads();

        // ---- final reduce over 32 k-chunks + tanh + store ----
        float s = xp;
        const float* pr = part + (warp * 32 + lane) * PART_STRIDE;
#pragma unroll
        for (int g = 0; g < 8; ++g) {
            float4 p = *(const float4*)(pr + g * 4);
            s += (p.x + p.y) + (p.z + p.w);
        }
        out[orow] = tanhf(s);

        // ---- group barrier: counter arrive + single-thread acquire poll ----
        __syncthreads();   // all STG issued; also protects hs/part reuse
        if (tid == 0) {
            asm volatile("red.release.gpu.add.u32 [%0], 1;" :: "l"(ctr) : "memory");
            const unsigned target = 32u * (unsigned)(t + 1);
            unsigned v;
            int spins = 0;
            while (true) {
                asm volatile("ld.acquire.gpu.u32 %0, [%1];" : "=r"(v) : "l"(ctr) : "memory");
                if (v >= target) break;
                if (++spins > 2) __nanosleep(32);
            }
        }
        __syncthreads();

        xp = xp_next;
    }
}

// ---------------------------------------------------------------------------
extern "C" void kernel_launch(void* const* d_in, const int* in_sizes, int n_in,
                              void* d_out, int out_size)
{
    (void)in_sizes; (void)n_in; (void)out_size;
    const float* x  = (const float*)d_in[0];
    const float* h0 = (const float*)d_in[1];
    const float* Wx = (const float*)d_in[2];
    const float* Wh = (const float*)d_in[3];
    float* out = (float*)d_out;

    dim3 g1(D_DIM / 64, (B_DIM * L_DIM) / 128);
    gemm_xw_kernel<<<g1, 256>>>(x, Wx, out);

    init_flags_kernel<<<1, 32>>>();
    size_t smem_bytes = (size_t)SMEM2_FLOATS * sizeof(float);
    cudaFuncSetAttribute(rnn_steps_kernel,
                         cudaFuncAttributeMaxDynamicSharedMemorySize,
                         (int)smem_bytes);
    rnn_steps_kernel<<<NB, TPB, smem_bytes>>>(out, h0, Wh);
}